// round 1
// baseline (speedup 1.0000x reference)
#include <cuda_runtime.h>

#define BB   64
#define LPROG 25
#define DD   128
#define NPOS 196
#define IMG  (DD*NPOS)      // 25088 floats per image state

typedef unsigned long long ull;

// ---------------- device scratch (no allocs allowed) ----------------
__device__ float g_T1 [BB*IMG];
__device__ float g_V  [BB*IMG];
__device__ float g_OUT[BB*IMG];
__device__ float g_SAV[BB*IMG];
__device__ float g_X  [BB*IMG];
__device__ float g_H  [BB*IMG];
__device__ float g_FLAT[BB*25088];   // 512*49 per image
__device__ float g_FC1[BB*1024];

// transposed weights: [bank][ic][k][oc]  (oc fastest)
__device__ float g_stem1t[1024*9*128];
__device__ float g_stem2t[128*9*128];
__device__ float g_uw1t[11*128*9*128];
__device__ float g_uw2t[11*128*9*128];
__device__ float g_bw1t[6*128*9*128];
__device__ float g_bw2t[6*128*9*128];
__device__ float g_bwpt[6*256*128];  // 1x1, [pi][ic(256)][oc(128)]
__device__ float g_clst[128*512];    // 1x1, [ic(128)][oc(512)]

// ---------------- f32x2 helpers ----------------
__device__ __forceinline__ ull pack2(float lo, float hi){
    ull r; asm("mov.b64 %0, {%1, %2};" : "=l"(r) : "f"(lo), "f"(hi)); return r;
}
__device__ __forceinline__ void fma2(ull &d, ull a, ull b){
    asm("fma.rn.f32x2 %0, %1, %2, %0;" : "+l"(d) : "l"(a), "l"(b));
}
__device__ __forceinline__ void unpack2(ull v, float &lo, float &hi){
    asm("mov.b64 {%0, %1}, %2;" : "=f"(lo), "=f"(hi) : "l"(v));
}

// ---------------- weight transpose:  src [nb][OC][IC][KK] -> dst [nb][IC][KK][OC] ----------------
__device__ __forceinline__ void tr_core(const float* __restrict__ src, float* __restrict__ dst,
                                        int nb, int OC, int IC, int KK){
    int total = nb*OC*IC*KK;
    for (int i = blockIdx.x*blockDim.x + threadIdx.x; i < total; i += gridDim.x*blockDim.x){
        int oc = i % OC;
        int r  = i / OC;
        int k  = r % KK; r /= KK;
        int ic = r % IC;
        int bank = r / IC;
        dst[i] = src[((bank*OC + oc)*IC + ic)*KK + k];
    }
}
__global__ void tr_stem1_k(const float* s){ tr_core(s, g_stem1t, 1, 128, 1024, 9); }
__global__ void tr_stem2_k(const float* s){ tr_core(s, g_stem2t, 1, 128, 128, 9); }
__global__ void tr_uw1_k  (const float* s){ tr_core(s, g_uw1t, 11, 128, 128, 9); }
__global__ void tr_uw2_k  (const float* s){ tr_core(s, g_uw2t, 11, 128, 128, 9); }
__global__ void tr_bw1_k  (const float* s){ tr_core(s, g_bw1t,  6, 128, 128, 9); }
__global__ void tr_bw2_k  (const float* s){ tr_core(s, g_bw2t,  6, 128, 128, 9); }
__global__ void tr_bwp_k  (const float* s){ tr_core(s, g_bwpt,  6, 128, 256, 1); }
__global__ void tr_cls_k  (const float* s){ tr_core(s, g_clst,  1, 512, 128, 1); }

// ---------------- generic 3x3 conv core ----------------
// block: 128 threads; threads t<98 own positions (t, t+98); 32 output channels
// per block as 16 f32x2 oc-pairs.  wt layout: [IC][9][128].
template<int IC>
__device__ void conv3x3_core(const float* __restrict__ src,   // [IC][196]
                             const float* __restrict__ wt,    // [IC][9][128]
                             int oc0,
                             const float* __restrict__ bias,  // [128]
                             const float* resid,              // [128][196] or null (may alias dst)
                             float* dst,                      // [128][196]
                             bool relu_out)
{
    __shared__ float s_in[8][16][16];
    __shared__ __align__(16) float s_w[8][9][32];
    const int t = threadIdx.x;
    ull acc0[16], acc1[16];
#pragma unroll
    for (int j = 0; j < 16; j++){ acc0[j] = 0ull; acc1[j] = 0ull; }
    const int p0 = t, p1 = t + 98;
    const int y0 = p0/14, x0 = p0 - y0*14;
    const int y1 = p1/14, x1 = p1 - y1*14;
    const bool active = (t < 98);

    for (int ic0 = 0; ic0 < IC; ic0 += 8){
        // input chunk (zero-padded 16x16 per channel)
#pragma unroll 4
        for (int i = t; i < 8*256; i += 128){
            int ic = i >> 8, r = i & 255, yy = r >> 4, xx = r & 15;
            float v = 0.f;
            if (yy >= 1 && yy <= 14 && xx >= 1 && xx <= 14)
                v = src[(ic0+ic)*196 + (yy-1)*14 + (xx-1)];
            s_in[ic][yy][xx] = v;
        }
        // weights (coalesced gmem, conflict-free STS)
#pragma unroll
        for (int i = t; i < 8*9*32; i += 128){
            int oc = i & 31, r = i >> 5, k = r % 9, ic = r / 9;
            s_w[ic][k][oc] = wt[((ic0+ic)*9 + k)*128 + oc0 + oc];
        }
        __syncthreads();
        if (active){
#pragma unroll 1
            for (int ic = 0; ic < 8; ic++){
                ull ap[9], bp[9];
#pragma unroll
                for (int ky = 0; ky < 3; ky++)
#pragma unroll
                    for (int kx = 0; kx < 3; kx++){
                        float av = s_in[ic][y0+ky][x0+kx];
                        float bv = s_in[ic][y1+ky][x1+kx];
                        ap[ky*3+kx] = pack2(av, av);
                        bp[ky*3+kx] = pack2(bv, bv);
                    }
#pragma unroll
                for (int j = 0; j < 16; j++){
#pragma unroll
                    for (int k = 0; k < 9; k++){
                        ull wp = *reinterpret_cast<const ull*>(&s_w[ic][k][2*j]);
                        fma2(acc0[j], ap[k], wp);
                        fma2(acc1[j], bp[k], wp);
                    }
                }
            }
        }
        __syncthreads();
    }
    if (active){
#pragma unroll
        for (int j = 0; j < 16; j++){
            int oc = oc0 + 2*j;
            float a0, a1, c0, c1;
            unpack2(acc0[j], a0, a1);
            unpack2(acc1[j], c0, c1);
            float bz0 = bias[oc], bz1 = bias[oc+1];
            a0 += bz0; a1 += bz1; c0 += bz0; c1 += bz1;
            if (resid){
                a0 += resid[oc*196+p0];     a1 += resid[(oc+1)*196+p0];
                c0 += resid[oc*196+p1];     c1 += resid[(oc+1)*196+p1];
            }
            if (relu_out){
                a0 = fmaxf(a0,0.f); a1 = fmaxf(a1,0.f);
                c0 = fmaxf(c0,0.f); c1 = fmaxf(c1,0.f);
            }
            dst[oc*196+p0]     = a0;  dst[(oc+1)*196+p0] = a1;
            dst[oc*196+p1]     = c0;  dst[(oc+1)*196+p1] = c1;
        }
    }
}

// ---------------- stem ----------------
__global__ void stem1_kernel(const float* __restrict__ feats, const float* __restrict__ b1){
    int b = blockIdx.y;
    conv3x3_core<1024>(feats + b*1024*196, g_stem1t, blockIdx.x*32, b1, nullptr,
                       g_T1 + b*IMG, true);
}
__global__ void stem2_kernel(const float* __restrict__ b2){
    int b = blockIdx.y;
    conv3x3_core<128>(g_T1 + b*IMG, g_stem2t, blockIdx.x*32, b2, nullptr,
                      g_V + b*IMG, true);
}

// ---------------- program state init: OUT = SAV = V ----------------
__global__ void init_kernel(){
    int n = BB*IMG/4;
    for (int i = blockIdx.x*blockDim.x + threadIdx.x; i < n; i += gridDim.x*blockDim.x){
        float4 v = ((const float4*)g_V)[i];
        ((float4*)g_OUT)[i] = v;
        ((float4*)g_SAV)[i] = v;
    }
}

// ---------------- program step kernels ----------------
// token decode: <4 noop | ==4 scene (pi=0) | 5..14 unary (pi=tok-4) | 15..20 binary (pi=tok-15)

__global__ void scene_copy_kernel(const int* __restrict__ programs, int tpos){
    int b = blockIdx.x;
    if (programs[b*LPROG + tpos] != 4) return;
    const float4* o = (const float4*)(g_OUT + b*IMG);
    float4* s = (float4*)(g_SAV + b*IMG);
    for (int i = threadIdx.x; i < IMG/4; i += blockDim.x) s[i] = o[i];
}

// binary 1x1 projection: X = relu(Wp @ concat(OUT,SAV) + bp)
__global__ void binproj_kernel(const int* __restrict__ programs, int tpos,
                               const float* __restrict__ bbp){
    int b = blockIdx.y;
    int tok = programs[b*LPROG + tpos];
    if (tok < 15) return;
    int pi = tok - 15;
    const float* wt = g_bwpt + pi*256*128;
    const int oc0 = blockIdx.x*32;
    __shared__ float s_in[16][196];
    __shared__ __align__(16) float s_w[16][32];
    const int t = threadIdx.x;
    ull acc0[16], acc1[16];
#pragma unroll
    for (int j = 0; j < 16; j++){ acc0[j] = 0ull; acc1[j] = 0ull; }
    const int p0 = t, p1 = t + 98;
    const bool active = (t < 98);
    const float* outb = g_OUT + b*IMG;
    const float* savb = g_SAV + b*IMG;

    for (int icg = 0; icg < 16; icg++){
        const float* srcp = (icg < 8 ? outb : savb) + ((icg & 7)*16)*196;
        for (int i = t; i < 16*196; i += 128){
            int ic = i/196, p = i - ic*196;
            s_in[ic][p] = srcp[ic*196 + p];
        }
        for (int i = t; i < 512; i += 128){
            int oc = i & 31, ic = i >> 5;
            s_w[ic][oc] = wt[(icg*16 + ic)*128 + oc0 + oc];
        }
        __syncthreads();
        if (active){
#pragma unroll 4
            for (int ic = 0; ic < 16; ic++){
                float av = s_in[ic][p0], bv = s_in[ic][p1];
                ull ap = pack2(av, av), bp = pack2(bv, bv);
#pragma unroll
                for (int j = 0; j < 16; j++){
                    ull wp = *reinterpret_cast<const ull*>(&s_w[ic][2*j]);
                    fma2(acc0[j], ap, wp);
                    fma2(acc1[j], bp, wp);
                }
            }
        }
        __syncthreads();
    }
    if (active){
        float* dst = g_X + b*IMG;
#pragma unroll
        for (int j = 0; j < 16; j++){
            int oc = oc0 + 2*j;
            float a0, a1, c0, c1;
            unpack2(acc0[j], a0, a1);
            unpack2(acc1[j], c0, c1);
            float bz0 = bbp[pi*128 + oc], bz1 = bbp[pi*128 + oc + 1];
            a0 = fmaxf(a0+bz0, 0.f); a1 = fmaxf(a1+bz1, 0.f);
            c0 = fmaxf(c0+bz0, 0.f); c1 = fmaxf(c1+bz1, 0.f);
            dst[oc*196+p0] = a0; dst[(oc+1)*196+p0] = a1;
            dst[oc*196+p1] = c0; dst[(oc+1)*196+p1] = c1;
        }
    }
}

__device__ __forceinline__ bool select_step(int tok, int b,
    const float* ubias, const float* bbias, const float* ut, const float* bt,
    const float*& src, const float*& wt, const float*& bias)
{
    if (tok < 4) return false;
    if (tok >= 15){
        int pi = tok - 15;
        src  = g_X + b*IMG;
        wt   = bt + pi*(128*9*128);
        bias = bbias + pi*128;
    } else {
        int pi = (tok == 4) ? 0 : (tok - 4);
        src  = (tok == 4 ? g_V : g_OUT) + b*IMG;
        wt   = ut + pi*(128*9*128);
        bias = ubias + pi*128;
    }
    return true;
}

// H = relu(conv1(src))
__global__ void stepA_kernel(const int* __restrict__ programs, int tpos,
                             const float* __restrict__ ub1, const float* __restrict__ bb1){
    int b = blockIdx.y;
    int tok = programs[b*LPROG + tpos];
    const float *src, *wt, *bias;
    if (!select_step(tok, b, ub1, bb1, g_uw1t, g_bw1t, src, wt, bias)) return;
    conv3x3_core<128>(src, wt, blockIdx.x*32, bias, nullptr, g_H + b*IMG, true);
}
// OUT = relu(src + conv2(H))
__global__ void stepB_kernel(const int* __restrict__ programs, int tpos,
                             const float* __restrict__ ub2, const float* __restrict__ bb2){
    int b = blockIdx.y;
    int tok = programs[b*LPROG + tpos];
    const float *src, *wt, *bias;
    if (!select_step(tok, b, ub2, bb2, g_uw2t, g_bw2t, src, wt, bias)) return;
    conv3x3_core<128>(g_H + b*IMG, wt, blockIdx.x*32, bias, src, g_OUT + b*IMG, true);
}

// ---------------- classifier: 1x1 conv 128->512 + relu + maxpool2 -> FLAT ----------------
__global__ void cls_kernel(const float* __restrict__ cls_b){
    int b = blockIdx.y;
    const int oc0 = blockIdx.x*32;
    __shared__ float s_in[16][196];
    __shared__ __align__(16) float s_w[16][32];
    __shared__ float s_c[32][196];
    const int t = threadIdx.x;
    ull acc0[16], acc1[16];
#pragma unroll
    for (int j = 0; j < 16; j++){ acc0[j] = 0ull; acc1[j] = 0ull; }
    const int p0 = t, p1 = t + 98;
    const bool active = (t < 98);
    const float* srcb = g_OUT + b*IMG;

    for (int icg = 0; icg < 8; icg++){
        for (int i = t; i < 16*196; i += 128){
            int ic = i/196, p = i - ic*196;
            s_in[ic][p] = srcb[(icg*16 + ic)*196 + p];
        }
        for (int i = t; i < 512; i += 128){
            int oc = i & 31, ic = i >> 5;
            s_w[ic][oc] = g_clst[(icg*16 + ic)*512 + oc0 + oc];
        }
        __syncthreads();
        if (active){
#pragma unroll 4
            for (int ic = 0; ic < 16; ic++){
                float av = s_in[ic][p0], bv = s_in[ic][p1];
                ull ap = pack2(av, av), bp = pack2(bv, bv);
#pragma unroll
                for (int j = 0; j < 16; j++){
                    ull wp = *reinterpret_cast<const ull*>(&s_w[ic][2*j]);
                    fma2(acc0[j], ap, wp);
                    fma2(acc1[j], bp, wp);
                }
            }
        }
        __syncthreads();
    }
    if (active){
#pragma unroll
        for (int j = 0; j < 16; j++){
            int oc = oc0 + 2*j;
            float a0, a1, c0, c1;
            unpack2(acc0[j], a0, a1);
            unpack2(acc1[j], c0, c1);
            float bz0 = cls_b[oc], bz1 = cls_b[oc+1];
            s_c[2*j  ][p0] = fmaxf(a0+bz0, 0.f);
            s_c[2*j+1][p0] = fmaxf(a1+bz1, 0.f);
            s_c[2*j  ][p1] = fmaxf(c0+bz0, 0.f);
            s_c[2*j+1][p1] = fmaxf(c1+bz1, 0.f);
        }
    }
    __syncthreads();
    // 2x2 maxpool -> flat [ch*49 + py*7 + px]
    for (int i = t; i < 32*49; i += 128){
        int ocl = i/49, cell = i - ocl*49;
        int py = cell/7, px = cell - py*7;
        int base = 28*py + 2*px;
        float m = fmaxf(fmaxf(s_c[ocl][base], s_c[ocl][base+1]),
                        fmaxf(s_c[ocl][base+14], s_c[ocl][base+15]));
        g_FLAT[b*25088 + (oc0 + ocl)*49 + cell] = m;
    }
}

// ---------------- fc1: [64,25088] x [1024,25088]^T, k-split with atomics ----------------
__global__ void zero_fc1(){
    int i = blockIdx.x*blockDim.x + threadIdx.x;
    if (i < BB*1024) g_FC1[i] = 0.f;
}
__global__ void fc1_kernel(const float* __restrict__ w){
    int n0 = blockIdx.x*64;
    int k0 = blockIdx.y*1568;
    __shared__ float sA[64][33];
    __shared__ float sB[64][33];
    const int t = threadIdx.x;
    const int tx = t & 15, ty = t >> 4;
    float acc[4][4] = {};
    for (int kk = 0; kk < 1568; kk += 32){
        for (int i = t; i < 2048; i += 256){
            int row = i >> 5, k = i & 31;
            sA[row][k] = g_FLAT[row*25088 + k0 + kk + k];
            sB[row][k] = w[(n0+row)*25088 + k0 + kk + k];
        }
        __syncthreads();
#pragma unroll 8
        for (int k = 0; k < 32; k++){
            float a[4], bv[4];
#pragma unroll
            for (int i = 0; i < 4; i++) a[i] = sA[ty*4+i][k];
#pragma unroll
            for (int j = 0; j < 4; j++) bv[j] = sB[tx*4+j][k];
#pragma unroll
            for (int i = 0; i < 4; i++)
#pragma unroll
                for (int j = 0; j < 4; j++) acc[i][j] += a[i]*bv[j];
        }
        __syncthreads();
    }
#pragma unroll
    for (int i = 0; i < 4; i++)
#pragma unroll
        for (int j = 0; j < 4; j++)
            atomicAdd(&g_FC1[(ty*4+i)*1024 + n0 + tx*4 + j], acc[i][j]);
}

// ---------------- fc2: out = relu(fc1+b1) @ fc2_w^T + b2 ----------------
__global__ void fc2_kernel(const float* __restrict__ fc1_b, const float* __restrict__ w2,
                           const float* __restrict__ b2, float* __restrict__ out){
    int b = blockIdx.x;
    const int t = threadIdx.x;
    int n2 = t >> 3, kl = t & 7;
    float acc = 0.f;
    for (int k = kl; k < 1024; k += 8)
        acc += fmaxf(g_FC1[b*1024 + k] + fc1_b[k], 0.f) * w2[n2*1024 + k];
    __shared__ float red[256];
    red[t] = acc;
    __syncthreads();
    if (kl == 0){
        float s = red[t];
#pragma unroll
        for (int q = 1; q < 8; q++) s += red[t+q];
        out[b*32 + n2] = s + b2[n2];
    }
}

// ---------------- launch ----------------
extern "C" void kernel_launch(void* const* d_in, const int* in_sizes, int n_in,
                              void* d_out, int out_size){
    const float* feats    = (const float*)d_in[0];
    const int*   programs = (const int*)  d_in[1];
    const float* stem_w1  = (const float*)d_in[2];
    const float* stem_b1  = (const float*)d_in[3];
    const float* stem_w2  = (const float*)d_in[4];
    const float* stem_b2  = (const float*)d_in[5];
    const float* uw1      = (const float*)d_in[6];
    const float* ub1      = (const float*)d_in[7];
    const float* uw2      = (const float*)d_in[8];
    const float* ub2      = (const float*)d_in[9];
    const float* bwp      = (const float*)d_in[10];
    const float* bbp      = (const float*)d_in[11];
    const float* bw1      = (const float*)d_in[12];
    const float* bb1      = (const float*)d_in[13];
    const float* bw2      = (const float*)d_in[14];
    const float* bb2      = (const float*)d_in[15];
    const float* cls_w    = (const float*)d_in[16];
    const float* cls_b    = (const float*)d_in[17];
    const float* fc1_w    = (const float*)d_in[18];
    const float* fc1_b    = (const float*)d_in[19];
    const float* fc2_w    = (const float*)d_in[20];
    const float* fc2_b    = (const float*)d_in[21];
    float* out = (float*)d_out;

    // weight layout transforms (deterministic, every call)
    tr_stem1_k<<<1024, 256>>>(stem_w1);
    tr_stem2_k<<<256,  256>>>(stem_w2);
    tr_uw1_k  <<<1024, 256>>>(uw1);
    tr_uw2_k  <<<1024, 256>>>(uw2);
    tr_bw1_k  <<<1024, 256>>>(bw1);
    tr_bw2_k  <<<1024, 256>>>(bw2);
    tr_bwp_k  <<<256,  256>>>(bwp);
    tr_cls_k  <<<256,  256>>>(cls_w);

    dim3 cgrid(4, BB);
    stem1_kernel<<<cgrid, 128>>>(feats, stem_b1);
    stem2_kernel<<<cgrid, 128>>>(stem_b2);
    init_kernel<<<512, 256>>>();

    for (int step = 0; step < LPROG; step++){
        int tpos = LPROG - 1 - step;              // scan over reversed program
        scene_copy_kernel<<<BB, 256>>>(programs, tpos);
        binproj_kernel<<<cgrid, 128>>>(programs, tpos, bbp);
        stepA_kernel<<<cgrid, 128>>>(programs, tpos, ub1, bb1);
        stepB_kernel<<<cgrid, 128>>>(programs, tpos, ub2, bb2);
    }

    cls_kernel<<<dim3(16, BB), 128>>>(cls_b);
    zero_fc1<<<256, 256>>>();
    fc1_kernel<<<dim3(16, 16), 256>>>(fc1_w);
    fc2_kernel<<<BB, 256>>>(fc1_b, fc2_w, fc2_b, out);
}

// round 2
// speedup vs baseline: 1.6200x; 1.6200x over previous
#include <cuda_runtime.h>

#define BB    64
#define LPROG 25
#define IMG   (128*196)     // 25088 floats per image state

typedef unsigned long long ull;

// ---------------- device scratch (no allocs allowed) ----------------
__device__ float g_V  [BB*IMG];
__device__ float g_OUT[BB*IMG];
__device__ float g_SAV[BB*IMG];
__device__ float g_X  [BB*IMG];
__device__ float g_H  [BB*IMG];     // also reused as stem temp T1
__device__ float g_FLAT[BB*25088];  // 512*49 per image
__device__ float g_FC1[BB*1024];

// transposed weights: [bank][ic][k][oc]  (oc fastest)
__device__ float g_stem1t[1024*9*128];
__device__ float g_stem2t[128*9*128];
__device__ float g_uw1t[11*128*9*128];
__device__ float g_uw2t[11*128*9*128];
__device__ float g_bw1t[6*128*9*128];
__device__ float g_bw2t[6*128*9*128];
__device__ float g_bwpt[6*256*128];  // 1x1, [pi][ic(256)][oc(128)]
__device__ float g_clst[128*512];    // 1x1, [ic(128)][oc(512)]

// ---------------- f32x2 helpers ----------------
__device__ __forceinline__ ull pack2(float lo, float hi){
    ull r; asm("mov.b64 %0, {%1, %2};" : "=l"(r) : "f"(lo), "f"(hi)); return r;
}
__device__ __forceinline__ void fma2(ull &d, ull a, ull b){
    asm("fma.rn.f32x2 %0, %1, %2, %0;" : "+l"(d) : "l"(a), "l"(b));
}
__device__ __forceinline__ void unpack2(ull v, float &lo, float &hi){
    asm("mov.b64 {%0, %1}, %2;" : "=f"(lo), "=f"(hi) : "l"(v));
}

// ---------------- weight transpose:  src [nb][OC][IC][KK] -> dst [nb][IC][KK][OC] ----------------
__device__ __forceinline__ void tr_core(const float* __restrict__ src, float* __restrict__ dst,
                                        int nb, int OC, int IC, int KK){
    int total = nb*OC*IC*KK;
    for (int i = blockIdx.x*blockDim.x + threadIdx.x; i < total; i += gridDim.x*blockDim.x){
        int oc = i % OC;
        int r  = i / OC;
        int k  = r % KK; r /= KK;
        int ic = r % IC;
        int bank = r / IC;
        dst[i] = src[((bank*OC + oc)*IC + ic)*KK + k];
    }
}
__global__ void tr_stem1_k(const float* s){ tr_core(s, g_stem1t, 1, 128, 1024, 9); }
__global__ void tr_stem2_k(const float* s){ tr_core(s, g_stem2t, 1, 128, 128, 9); }
__global__ void tr_uw1_k  (const float* s){ tr_core(s, g_uw1t, 11, 128, 128, 9); }
__global__ void tr_uw2_k  (const float* s){ tr_core(s, g_uw2t, 11, 128, 128, 9); }
__global__ void tr_bw1_k  (const float* s){ tr_core(s, g_bw1t,  6, 128, 128, 9); }
__global__ void tr_bw2_k  (const float* s){ tr_core(s, g_bw2t,  6, 128, 128, 9); }
__global__ void tr_bwp_k  (const float* s){ tr_core(s, g_bwpt,  6, 128, 256, 1); }
__global__ void tr_cls_k  (const float* s){ tr_core(s, g_clst,  1, 512, 128, 1); }

// ---------------- shared memory union for the persistent kernel ----------------
struct SmemConv { float in[8][16][16]; float w[8][9][32]; };
struct SmemProj { float in[16][196];   float w[16][32];   };
union  SmemU { SmemConv c; SmemProj p; };

// cluster-wide phase boundary: publish writes + invalidate L1, then barrier
__device__ __forceinline__ void csync(){
    __threadfence();   // gpu scope >= cluster: orders STG, emits CCTL.IVALL
    asm volatile("barrier.cluster.arrive.aligned;" ::: "memory");
    asm volatile("barrier.cluster.wait.aligned;"   ::: "memory");
}

// ---------------- 3x3 conv slice: this CTA computes 32 output channels ----------------
// 256 threads = two 128-thread halves; half h covers oc [oc0+16h, oc0+16h+16).
// Within a half, thread tl<98 owns positions (tl, tl+98), 8 oc-pairs each.
// wt layout: [IC][9][128] (oc fastest).
__device__ void conv3x3_p(SmemU* sm, const float* __restrict__ src,
                          const float* __restrict__ wt, int oc0,
                          const float* __restrict__ bias,
                          const float* resid, float* dst,
                          float* dst2, float* dst3, int IC)
{
    const int t   = threadIdx.x;
    const int hid = t >> 7;
    const int tl  = t & 127;
    ull acc0[8], acc1[8];
#pragma unroll
    for (int j = 0; j < 8; j++){ acc0[j] = 0ull; acc1[j] = 0ull; }
    const int p0 = tl, p1 = tl + 98;
    const int y0 = p0/14, x0 = p0 - y0*14;
    const int y1 = p1/14, x1 = p1 - y1*14;
    const bool act = (tl < 98);

    for (int ic0 = 0; ic0 < IC; ic0 += 8){
        // stage input chunk (zero-padded 16x16 per channel)
#pragma unroll 4
        for (int i = t; i < 8*256; i += 256){
            int ic = i >> 8, r = i & 255, yy = r >> 4, xx = r & 15;
            float v = 0.f;
            if (yy >= 1 && yy <= 14 && xx >= 1 && xx <= 14)
                v = src[(ic0+ic)*196 + (yy-1)*14 + (xx-1)];
            sm->c.in[ic][yy][xx] = v;
        }
        // stage this CTA's 32-oc weight slice
#pragma unroll
        for (int i = t; i < 8*9*32; i += 256){
            int oc = i & 31, r = i >> 5, k = r % 9, ic = r / 9;
            sm->c.w[ic][k][oc] = wt[((ic0+ic)*9 + k)*128 + oc0 + oc];
        }
        __syncthreads();
        if (act){
#pragma unroll 1
            for (int ic = 0; ic < 8; ic++){
                ull ap[9], bp[9];
#pragma unroll
                for (int ky = 0; ky < 3; ky++)
#pragma unroll
                    for (int kx = 0; kx < 3; kx++){
                        float av = sm->c.in[ic][y0+ky][x0+kx];
                        float bv = sm->c.in[ic][y1+ky][x1+kx];
                        ap[ky*3+kx] = pack2(av, av);
                        bp[ky*3+kx] = pack2(bv, bv);
                    }
#pragma unroll
                for (int g = 0; g < 4; g++){
#pragma unroll
                    for (int k = 0; k < 9; k++){
                        ulonglong2 w2 = *reinterpret_cast<const ulonglong2*>(
                            &sm->c.w[ic][k][hid*16 + g*4]);
                        fma2(acc0[2*g  ], ap[k], w2.x);
                        fma2(acc0[2*g+1], ap[k], w2.y);
                        fma2(acc1[2*g  ], bp[k], w2.x);
                        fma2(acc1[2*g+1], bp[k], w2.y);
                    }
                }
            }
        }
        __syncthreads();
    }
    if (act){
#pragma unroll
        for (int j = 0; j < 8; j++){
            int oc = oc0 + hid*16 + 2*j;
            float a0, a1, c0, c1;
            unpack2(acc0[j], a0, a1);
            unpack2(acc1[j], c0, c1);
            float bz0 = bias[oc], bz1 = bias[oc+1];
            a0 += bz0; a1 += bz1; c0 += bz0; c1 += bz1;
            if (resid){
                a0 += resid[oc*196+p0];     a1 += resid[(oc+1)*196+p0];
                c0 += resid[oc*196+p1];     c1 += resid[(oc+1)*196+p1];
            }
            a0 = fmaxf(a0,0.f); a1 = fmaxf(a1,0.f);
            c0 = fmaxf(c0,0.f); c1 = fmaxf(c1,0.f);
            dst[oc*196+p0] = a0;  dst[(oc+1)*196+p0] = a1;
            dst[oc*196+p1] = c0;  dst[(oc+1)*196+p1] = c1;
            if (dst2){
                dst2[oc*196+p0] = a0; dst2[(oc+1)*196+p0] = a1;
                dst2[oc*196+p1] = c0; dst2[(oc+1)*196+p1] = c1;
            }
            if (dst3){
                dst3[oc*196+p0] = a0; dst3[(oc+1)*196+p0] = a1;
                dst3[oc*196+p1] = c0; dst3[(oc+1)*196+p1] = c1;
            }
        }
    }
}

// ---------------- binary 1x1 projection slice: 32 oc from concat(OUT,SAV) ----------------
__device__ void proj_p(SmemU* sm, const float* __restrict__ A, const float* __restrict__ S,
                       const float* __restrict__ wt, int oc0,
                       const float* __restrict__ bias, float* dst)
{
    const int t = threadIdx.x;
    const bool act = (t < 196);
    ull acc[16];
#pragma unroll
    for (int j = 0; j < 16; j++) acc[j] = 0ull;

    for (int icg = 0; icg < 16; icg++){
        const float* s = (icg < 8 ? A : S) + (icg & 7)*16*196;
        for (int i = t; i < 16*196; i += 256){
            int ic = i/196, p = i - ic*196;
            sm->p.in[ic][p] = s[ic*196 + p];
        }
        for (int i = t; i < 512; i += 256){
            int oc = i & 31, ic = i >> 5;
            sm->p.w[ic][oc] = wt[(icg*16 + ic)*128 + oc0 + oc];
        }
        __syncthreads();
        if (act){
#pragma unroll 4
            for (int ic = 0; ic < 16; ic++){
                float a = sm->p.in[ic][t];
                ull ap = pack2(a, a);
#pragma unroll
                for (int g = 0; g < 8; g++){
                    ulonglong2 w2 = *reinterpret_cast<const ulonglong2*>(&sm->p.w[ic][g*4]);
                    fma2(acc[2*g  ], ap, w2.x);
                    fma2(acc[2*g+1], ap, w2.y);
                }
            }
        }
        __syncthreads();
    }
    if (act){
#pragma unroll
        for (int j = 0; j < 16; j++){
            int oc = oc0 + 2*j;
            float a0, a1;
            unpack2(acc[j], a0, a1);
            a0 = fmaxf(a0 + bias[oc],   0.f);
            a1 = fmaxf(a1 + bias[oc+1], 0.f);
            dst[oc*196+t]     = a0;
            dst[(oc+1)*196+t] = a1;
        }
    }
}

// ---------------- persistent program kernel: 64 images x 4-CTA clusters ----------------
__global__ void __cluster_dims__(4,1,1) __launch_bounds__(256, 2)
program_kernel(const float* __restrict__ feats, const int* __restrict__ programs,
               const float* __restrict__ stem_b1, const float* __restrict__ stem_b2,
               const float* __restrict__ ub1, const float* __restrict__ ub2,
               const float* __restrict__ bbp, const float* __restrict__ bb1,
               const float* __restrict__ bb2)
{
    __shared__ SmemU sm;
    const int cta = blockIdx.x;
    const int b   = cta >> 2;
    const int oc0 = (cta & 3) * 32;
    float* OUT = g_OUT + b*IMG;
    float* SAV = g_SAV + b*IMG;
    float* X   = g_X   + b*IMG;
    float* H   = g_H   + b*IMG;
    float* V   = g_V   + b*IMG;

    // stem: conv3x3(1024->128) -> relu -> conv3x3(128->128) -> relu; init OUT=SAV=V
    conv3x3_p(&sm, feats + b*1024*196, g_stem1t, oc0, stem_b1, nullptr,
              H, nullptr, nullptr, 1024);
    csync();
    conv3x3_p(&sm, H, g_stem2t, oc0, stem_b2, nullptr, V, OUT, SAV, 128);
    csync();

    // program walk (reverse token order, matching reference scan of prog[::-1])
    for (int tpos = LPROG-1; tpos >= 0; tpos--){
        int tok = programs[b*LPROG + tpos];
        if (tok < 4) continue;                   // no-op tokens: no phases, no barriers
        if (tok >= 15){                          // binary module
            int pi = tok - 15;
            proj_p(&sm, OUT, SAV, g_bwpt + pi*256*128, oc0, bbp + pi*128, X);
            csync();
            conv3x3_p(&sm, X, g_bw1t + pi*(128*9*128), oc0, bb1 + pi*128, nullptr,
                      H, nullptr, nullptr, 128);
            csync();
            conv3x3_p(&sm, H, g_bw2t + pi*(128*9*128), oc0, bb2 + pi*128, X,
                      OUT, nullptr, nullptr, 128);
            csync();
        } else {                                 // scene (4) or unary (5..14)
            int pi = (tok == 4) ? 0 : tok - 4;
            const float* src = (tok == 4) ? V : OUT;
            if (tok == 4){
                // saved = old out (own slice; completes before OUT overwritten next phase)
                for (int i = threadIdx.x; i < 32*196; i += 256){
                    int idx = oc0*196 + i;
                    SAV[idx] = OUT[idx];
                }
            }
            conv3x3_p(&sm, src, g_uw1t + pi*(128*9*128), oc0, ub1 + pi*128, nullptr,
                      H, nullptr, nullptr, 128);
            csync();
            conv3x3_p(&sm, H, g_uw2t + pi*(128*9*128), oc0, ub2 + pi*128, src,
                      OUT, nullptr, nullptr, 128);
            csync();
        }
    }
}

// ---------------- classifier: 1x1 conv 128->512 + relu + maxpool2 -> FLAT ----------------
__global__ void cls_kernel(const float* __restrict__ cls_b){
    int b = blockIdx.y;
    const int oc0 = blockIdx.x*32;
    __shared__ float s_in[16][196];
    __shared__ __align__(16) float s_w[16][32];
    __shared__ float s_c[32][196];
    const int t = threadIdx.x;
    ull acc0[16], acc1[16];
#pragma unroll
    for (int j = 0; j < 16; j++){ acc0[j] = 0ull; acc1[j] = 0ull; }
    const int p0 = t, p1 = t + 98;
    const bool active = (t < 98);
    const float* srcb = g_OUT + b*IMG;

    for (int icg = 0; icg < 8; icg++){
        for (int i = t; i < 16*196; i += 128){
            int ic = i/196, p = i - ic*196;
            s_in[ic][p] = srcb[(icg*16 + ic)*196 + p];
        }
        for (int i = t; i < 512; i += 128){
            int oc = i & 31, ic = i >> 5;
            s_w[ic][oc] = g_clst[(icg*16 + ic)*512 + oc0 + oc];
        }
        __syncthreads();
        if (active){
#pragma unroll 4
            for (int ic = 0; ic < 16; ic++){
                float av = s_in[ic][p0], bv = s_in[ic][p1];
                ull ap = pack2(av, av), bp = pack2(bv, bv);
#pragma unroll
                for (int g = 0; g < 8; g++){
                    ulonglong2 w2 = *reinterpret_cast<const ulonglong2*>(&s_w[ic][g*4]);
                    fma2(acc0[2*g  ], ap, w2.x);
                    fma2(acc0[2*g+1], ap, w2.y);
                    fma2(acc1[2*g  ], bp, w2.x);
                    fma2(acc1[2*g+1], bp, w2.y);
                }
            }
        }
        __syncthreads();
    }
    if (active){
#pragma unroll
        for (int j = 0; j < 16; j++){
            int oc = oc0 + 2*j;
            float a0, a1, c0, c1;
            unpack2(acc0[j], a0, a1);
            unpack2(acc1[j], c0, c1);
            float bz0 = cls_b[oc], bz1 = cls_b[oc+1];
            s_c[2*j  ][p0] = fmaxf(a0+bz0, 0.f);
            s_c[2*j+1][p0] = fmaxf(a1+bz1, 0.f);
            s_c[2*j  ][p1] = fmaxf(c0+bz0, 0.f);
            s_c[2*j+1][p1] = fmaxf(c1+bz1, 0.f);
        }
    }
    __syncthreads();
    // 2x2 maxpool -> flat [ch*49 + py*7 + px]
    for (int i = t; i < 32*49; i += 128){
        int ocl = i/49, cell = i - ocl*49;
        int py = cell/7, px = cell - py*7;
        int base = 28*py + 2*px;
        float m = fmaxf(fmaxf(s_c[ocl][base], s_c[ocl][base+1]),
                        fmaxf(s_c[ocl][base+14], s_c[ocl][base+15]));
        g_FLAT[b*25088 + (oc0 + ocl)*49 + cell] = m;
    }
}

// ---------------- fc1: [64,25088] x [1024,25088]^T, k-split with atomics ----------------
__global__ void zero_fc1(){
    int i = blockIdx.x*blockDim.x + threadIdx.x;
    if (i < BB*1024) g_FC1[i] = 0.f;
}
__global__ void fc1_kernel(const float* __restrict__ w){
    int n0 = blockIdx.x*64;
    int k0 = blockIdx.y*1568;
    __shared__ float sA[64][33];
    __shared__ float sB[64][33];
    const int t = threadIdx.x;
    const int tx = t & 15, ty = t >> 4;
    float acc[4][4] = {};
    for (int kk = 0; kk < 1568; kk += 32){
        for (int i = t; i < 2048; i += 256){
            int row = i >> 5, k = i & 31;
            sA[row][k] = g_FLAT[row*25088 + k0 + kk + k];
            sB[row][k] = w[(n0+row)*25088 + k0 + kk + k];
        }
        __syncthreads();
#pragma unroll 8
        for (int k = 0; k < 32; k++){
            float a[4], bv[4];
#pragma unroll
            for (int i = 0; i < 4; i++) a[i] = sA[ty*4+i][k];
#pragma unroll
            for (int j = 0; j < 4; j++) bv[j] = sB[tx*4+j][k];
#pragma unroll
            for (int i = 0; i < 4; i++)
#pragma unroll
                for (int j = 0; j < 4; j++) acc[i][j] += a[i]*bv[j];
        }
        __syncthreads();
    }
#pragma unroll
    for (int i = 0; i < 4; i++)
#pragma unroll
        for (int j = 0; j < 4; j++)
            atomicAdd(&g_FC1[(ty*4+i)*1024 + n0 + tx*4 + j], acc[i][j]);
}

// ---------------- fc2: out = relu(fc1+b1) @ fc2_w^T + b2 ----------------
__global__ void fc2_kernel(const float* __restrict__ fc1_b, const float* __restrict__ w2,
                           const float* __restrict__ b2, float* __restrict__ out){
    int b = blockIdx.x;
    const int t = threadIdx.x;
    int n2 = t >> 3, kl = t & 7;
    float acc = 0.f;
    for (int k = kl; k < 1024; k += 8)
        acc += fmaxf(g_FC1[b*1024 + k] + fc1_b[k], 0.f) * w2[n2*1024 + k];
    __shared__ float red[256];
    red[t] = acc;
    __syncthreads();
    if (kl == 0){
        float s = red[t];
#pragma unroll
        for (int q = 1; q < 8; q++) s += red[t+q];
        out[b*32 + n2] = s + b2[n2];
    }
}

// ---------------- launch ----------------
extern "C" void kernel_launch(void* const* d_in, const int* in_sizes, int n_in,
                              void* d_out, int out_size){
    const float* feats    = (const float*)d_in[0];
    const int*   programs = (const int*)  d_in[1];
    const float* stem_w1  = (const float*)d_in[2];
    const float* stem_b1  = (const float*)d_in[3];
    const float* stem_w2  = (const float*)d_in[4];
    const float* stem_b2  = (const float*)d_in[5];
    const float* uw1      = (const float*)d_in[6];
    const float* ub1      = (const float*)d_in[7];
    const float* uw2      = (const float*)d_in[8];
    const float* ub2      = (const float*)d_in[9];
    const float* bwp      = (const float*)d_in[10];
    const float* bbp      = (const float*)d_in[11];
    const float* bw1      = (const float*)d_in[12];
    const float* bb1      = (const float*)d_in[13];
    const float* bw2      = (const float*)d_in[14];
    const float* bb2      = (const float*)d_in[15];
    const float* cls_w    = (const float*)d_in[16];
    const float* cls_b    = (const float*)d_in[17];
    const float* fc1_w    = (const float*)d_in[18];
    const float* fc1_b    = (const float*)d_in[19];
    const float* fc2_w    = (const float*)d_in[20];
    const float* fc2_b    = (const float*)d_in[21];
    float* out = (float*)d_out;

    // weight layout transforms (deterministic, every call)
    tr_stem1_k<<<1024, 256>>>(stem_w1);
    tr_stem2_k<<<256,  256>>>(stem_w2);
    tr_uw1_k  <<<1024, 256>>>(uw1);
    tr_uw2_k  <<<1024, 256>>>(uw2);
    tr_bw1_k  <<<1024, 256>>>(bw1);
    tr_bw2_k  <<<1024, 256>>>(bw2);
    tr_bwp_k  <<<256,  256>>>(bwp);
    tr_cls_k  <<<256,  256>>>(cls_w);

    // one persistent cluster kernel runs stem + the entire per-image program
    program_kernel<<<BB*4, 256>>>(feats, programs, stem_b1, stem_b2,
                                  ub1, ub2, bbp, bb1, bb2);

    cls_kernel<<<dim3(16, BB), 128>>>(cls_b);
    zero_fc1<<<256, 256>>>();
    fc1_kernel<<<dim3(16, 16), 256>>>(fc1_w);
    fc2_kernel<<<BB, 256>>>(fc1_b, fc2_w, fc2_b, out);
}

// round 3
// speedup vs baseline: 1.6203x; 1.0002x over previous
#include <cuda_runtime.h>

#define BB    64
#define LPROG 25
#define IMG   (128*196)     // 25088 floats per image state

typedef unsigned long long ull;

// ---------------- device scratch (no allocs allowed) ----------------
__device__ float g_V  [BB*IMG];
__device__ float g_OUT[BB*IMG];
__device__ float g_SAV[BB*IMG];
__device__ float g_X  [BB*IMG];
__device__ float g_H  [BB*IMG];     // also reused as stem temp T1
__device__ float g_FLAT[BB*25088];  // 512*49 per image
__device__ float g_FC1[BB*1024];

// transposed weights: [bank][ic][k][oc]  (oc fastest)
__device__ float g_stem1t[1024*9*128];
__device__ float g_stem2t[128*9*128];
__device__ float g_uw1t[11*128*9*128];
__device__ float g_uw2t[11*128*9*128];
__device__ float g_bw1t[6*128*9*128];
__device__ float g_bw2t[6*128*9*128];
__device__ float g_bwpt[6*256*128];  // 1x1, [pi][ic(256)][oc(128)]
__device__ float g_clst[128*512];    // 1x1, [ic(128)][oc(512)]

// ---------------- f32x2 helpers ----------------
__device__ __forceinline__ ull pack2(float lo, float hi){
    ull r; asm("mov.b64 %0, {%1, %2};" : "=l"(r) : "f"(lo), "f"(hi)); return r;
}
__device__ __forceinline__ void fma2(ull &d, ull a, ull b){
    asm("fma.rn.f32x2 %0, %1, %2, %0;" : "+l"(d) : "l"(a), "l"(b));
}
__device__ __forceinline__ void unpack2(ull v, float &lo, float &hi){
    asm("mov.b64 {%0, %1}, %2;" : "=f"(lo), "=f"(hi) : "l"(v));
}

// ---------------- weight transpose:  src [nb][OC][IC][KK] -> dst [nb][IC][KK][OC] ----------------
__device__ __forceinline__ void tr_core(const float* __restrict__ src, float* __restrict__ dst,
                                        int nb, int OC, int IC, int KK){
    int total = nb*OC*IC*KK;
    for (int i = blockIdx.x*blockDim.x + threadIdx.x; i < total; i += gridDim.x*blockDim.x){
        int oc = i % OC;
        int r  = i / OC;
        int k  = r % KK; r /= KK;
        int ic = r % IC;
        int bank = r / IC;
        dst[i] = src[((bank*OC + oc)*IC + ic)*KK + k];
    }
}
__global__ void tr_stem1_k(const float* s){ tr_core(s, g_stem1t, 1, 128, 1024, 9); }
__global__ void tr_stem2_k(const float* s){ tr_core(s, g_stem2t, 1, 128, 128, 9); }
__global__ void tr_uw1_k  (const float* s){ tr_core(s, g_uw1t, 11, 128, 128, 9); }
__global__ void tr_uw2_k  (const float* s){ tr_core(s, g_uw2t, 11, 128, 128, 9); }
__global__ void tr_bw1_k  (const float* s){ tr_core(s, g_bw1t,  6, 128, 128, 9); }
__global__ void tr_bw2_k  (const float* s){ tr_core(s, g_bw2t,  6, 128, 128, 9); }
__global__ void tr_bwp_k  (const float* s){ tr_core(s, g_bwpt,  6, 128, 256, 1); }
__global__ void tr_cls_k  (const float* s){ tr_core(s, g_clst,  1, 512, 128, 1); }

// ---------------- shared memory union for the persistent kernel ----------------
struct SmemConv { float in[8][16][16]; float w[8][9][32]; };
struct SmemProj { float in[16][196];   float w[16][32];   };
union  SmemU { SmemConv c; SmemProj p; };

// cluster-wide phase boundary: publish writes + invalidate L1, then barrier
__device__ __forceinline__ void csync(){
    __threadfence();   // gpu scope >= cluster: orders STG, emits CCTL.IVALL
    asm volatile("barrier.cluster.arrive.aligned;" ::: "memory");
    asm volatile("barrier.cluster.wait.aligned;"   ::: "memory");
}

// ---------------- 3x3 conv slice: this CTA computes 32 output channels ----------------
// 256 threads = two 128-thread halves; half h covers oc [oc0+16h, oc0+16h+16).
// Within a half, thread tl<98 owns positions (tl, tl+98), 8 oc-pairs each.
// wt layout: [IC][9][128] (oc fastest).
__device__ void conv3x3_p(SmemU* sm, const float* __restrict__ src,
                          const float* __restrict__ wt, int oc0,
                          const float* __restrict__ bias,
                          const float* resid, float* dst,
                          float* dst2, float* dst3, int IC)
{
    const int t   = threadIdx.x;
    const int hid = t >> 7;
    const int tl  = t & 127;
    ull acc0[8], acc1[8];
#pragma unroll
    for (int j = 0; j < 8; j++){ acc0[j] = 0ull; acc1[j] = 0ull; }
    const int p0 = tl, p1 = tl + 98;
    const int y0 = p0/14, x0 = p0 - y0*14;
    const int y1 = p1/14, x1 = p1 - y1*14;
    const bool act = (tl < 98);

    for (int ic0 = 0; ic0 < IC; ic0 += 8){
        // stage input chunk (zero-padded 16x16 per channel)
#pragma unroll 4
        for (int i = t; i < 8*256; i += 256){
            int ic = i >> 8, r = i & 255, yy = r >> 4, xx = r & 15;
            float v = 0.f;
            if (yy >= 1 && yy <= 14 && xx >= 1 && xx <= 14)
                v = src[(ic0+ic)*196 + (yy-1)*14 + (xx-1)];
            sm->c.in[ic][yy][xx] = v;
        }
        // stage this CTA's 32-oc weight slice
#pragma unroll
        for (int i = t; i < 8*9*32; i += 256){
            int oc = i & 31, r = i >> 5, k = r % 9, ic = r / 9;
            sm->c.w[ic][k][oc] = wt[((ic0+ic)*9 + k)*128 + oc0 + oc];
        }
        __syncthreads();
        if (act){
#pragma unroll 1
            for (int ic = 0; ic < 8; ic++){
                ull ap[9], bp[9];
#pragma unroll
                for (int ky = 0; ky < 3; ky++)
#pragma unroll
                    for (int kx = 0; kx < 3; kx++){
                        float av = sm->c.in[ic][y0+ky][x0+kx];
                        float bv = sm->c.in[ic][y1+ky][x1+kx];
                        ap[ky*3+kx] = pack2(av, av);
                        bp[ky*3+kx] = pack2(bv, bv);
                    }
#pragma unroll
                for (int g = 0; g < 4; g++){
#pragma unroll
                    for (int k = 0; k < 9; k++){
                        ulonglong2 w2 = *reinterpret_cast<const ulonglong2*>(
                            &sm->c.w[ic][k][hid*16 + g*4]);
                        fma2(acc0[2*g  ], ap[k], w2.x);
                        fma2(acc0[2*g+1], ap[k], w2.y);
                        fma2(acc1[2*g  ], bp[k], w2.x);
                        fma2(acc1[2*g+1], bp[k], w2.y);
                    }
                }
            }
        }
        __syncthreads();
    }
    if (act){
#pragma unroll
        for (int j = 0; j < 8; j++){
            int oc = oc0 + hid*16 + 2*j;
            float a0, a1, c0, c1;
            unpack2(acc0[j], a0, a1);
            unpack2(acc1[j], c0, c1);
            float bz0 = bias[oc], bz1 = bias[oc+1];
            a0 += bz0; a1 += bz1; c0 += bz0; c1 += bz1;
            if (resid){
                a0 += resid[oc*196+p0];     a1 += resid[(oc+1)*196+p0];
                c0 += resid[oc*196+p1];     c1 += resid[(oc+1)*196+p1];
            }
            a0 = fmaxf(a0,0.f); a1 = fmaxf(a1,0.f);
            c0 = fmaxf(c0,0.f); c1 = fmaxf(c1,0.f);
            dst[oc*196+p0] = a0;  dst[(oc+1)*196+p0] = a1;
            dst[oc*196+p1] = c0;  dst[(oc+1)*196+p1] = c1;
            if (dst2){
                dst2[oc*196+p0] = a0; dst2[(oc+1)*196+p0] = a1;
                dst2[oc*196+p1] = c0; dst2[(oc+1)*196+p1] = c1;
            }
            if (dst3){
                dst3[oc*196+p0] = a0; dst3[(oc+1)*196+p0] = a1;
                dst3[oc*196+p1] = c0; dst3[(oc+1)*196+p1] = c1;
            }
        }
    }
}

// ---------------- binary 1x1 projection slice: 32 oc from concat(OUT,SAV) ----------------
__device__ void proj_p(SmemU* sm, const float* __restrict__ A, const float* __restrict__ S,
                       const float* __restrict__ wt, int oc0,
                       const float* __restrict__ bias, float* dst)
{
    const int t = threadIdx.x;
    const bool act = (t < 196);
    ull acc[16];
#pragma unroll
    for (int j = 0; j < 16; j++) acc[j] = 0ull;

    for (int icg = 0; icg < 16; icg++){
        const float* s = (icg < 8 ? A : S) + (icg & 7)*16*196;
        for (int i = t; i < 16*196; i += 256){
            int ic = i/196, p = i - ic*196;
            sm->p.in[ic][p] = s[ic*196 + p];
        }
        for (int i = t; i < 512; i += 256){
            int oc = i & 31, ic = i >> 5;
            sm->p.w[ic][oc] = wt[(icg*16 + ic)*128 + oc0 + oc];
        }
        __syncthreads();
        if (act){
#pragma unroll 4
            for (int ic = 0; ic < 16; ic++){
                float a = sm->p.in[ic][t];
                ull ap = pack2(a, a);
#pragma unroll
                for (int g = 0; g < 8; g++){
                    ulonglong2 w2 = *reinterpret_cast<const ulonglong2*>(&sm->p.w[ic][g*4]);
                    fma2(acc[2*g  ], ap, w2.x);
                    fma2(acc[2*g+1], ap, w2.y);
                }
            }
        }
        __syncthreads();
    }
    if (act){
#pragma unroll
        for (int j = 0; j < 16; j++){
            int oc = oc0 + 2*j;
            float a0, a1;
            unpack2(acc[j], a0, a1);
            a0 = fmaxf(a0 + bias[oc],   0.f);
            a1 = fmaxf(a1 + bias[oc+1], 0.f);
            dst[oc*196+t]     = a0;
            dst[(oc+1)*196+t] = a1;
        }
    }
}

// ---------------- persistent program kernel: 64 images x 4-CTA clusters ----------------
__global__ void __cluster_dims__(4,1,1) __launch_bounds__(256, 2)
program_kernel(const float* __restrict__ feats, const int* __restrict__ programs,
               const float* __restrict__ stem_b1, const float* __restrict__ stem_b2,
               const float* __restrict__ ub1, const float* __restrict__ ub2,
               const float* __restrict__ bbp, const float* __restrict__ bb1,
               const float* __restrict__ bb2)
{
    __shared__ SmemU sm;
    const int cta = blockIdx.x;
    const int b   = cta >> 2;
    const int oc0 = (cta & 3) * 32;
    float* OUT = g_OUT + b*IMG;
    float* SAV = g_SAV + b*IMG;
    float* X   = g_X   + b*IMG;
    float* H   = g_H   + b*IMG;
    float* V   = g_V   + b*IMG;

    // stem: conv3x3(1024->128) -> relu -> conv3x3(128->128) -> relu; init OUT=SAV=V
    conv3x3_p(&sm, feats + b*1024*196, g_stem1t, oc0, stem_b1, nullptr,
              H, nullptr, nullptr, 1024);
    csync();
    conv3x3_p(&sm, H, g_stem2t, oc0, stem_b2, nullptr, V, OUT, SAV, 128);
    csync();

    // program walk (reverse token order, matching reference scan of prog[::-1])
    for (int tpos = LPROG-1; tpos >= 0; tpos--){
        int tok = programs[b*LPROG + tpos];
        if (tok < 4) continue;                   // no-op tokens: no phases, no barriers
        if (tok >= 15){                          // binary module
            int pi = tok - 15;
            proj_p(&sm, OUT, SAV, g_bwpt + pi*256*128, oc0, bbp + pi*128, X);
            csync();
            conv3x3_p(&sm, X, g_bw1t + pi*(128*9*128), oc0, bb1 + pi*128, nullptr,
                      H, nullptr, nullptr, 128);
            csync();
            conv3x3_p(&sm, H, g_bw2t + pi*(128*9*128), oc0, bb2 + pi*128, X,
                      OUT, nullptr, nullptr, 128);
            csync();
        } else {                                 // scene (4) or unary (5..14)
            int pi = (tok == 4) ? 0 : tok - 4;
            const float* src = (tok == 4) ? V : OUT;
            if (tok == 4){
                // saved = old out (own slice; completes before OUT overwritten next phase)
                for (int i = threadIdx.x; i < 32*196; i += 256){
                    int idx = oc0*196 + i;
                    SAV[idx] = OUT[idx];
                }
            }
            conv3x3_p(&sm, src, g_uw1t + pi*(128*9*128), oc0, ub1 + pi*128, nullptr,
                      H, nullptr, nullptr, 128);
            csync();
            conv3x3_p(&sm, H, g_uw2t + pi*(128*9*128), oc0, ub2 + pi*128, src,
                      OUT, nullptr, nullptr, 128);
            csync();
        }
    }
}

// ---------------- classifier: 1x1 conv 128->512 + relu + maxpool2 -> FLAT ----------------
__global__ void cls_kernel(const float* __restrict__ cls_b){
    int b = blockIdx.y;
    const int oc0 = blockIdx.x*32;
    __shared__ float s_in[16][196];
    __shared__ __align__(16) float s_w[16][32];
    __shared__ float s_c[32][196];
    const int t = threadIdx.x;
    ull acc0[16], acc1[16];
#pragma unroll
    for (int j = 0; j < 16; j++){ acc0[j] = 0ull; acc1[j] = 0ull; }
    const int p0 = t, p1 = t + 98;
    const bool active = (t < 98);
    const float* srcb = g_OUT + b*IMG;

    for (int icg = 0; icg < 8; icg++){
        for (int i = t; i < 16*196; i += 128){
            int ic = i/196, p = i - ic*196;
            s_in[ic][p] = srcb[(icg*16 + ic)*196 + p];
        }
        for (int i = t; i < 512; i += 128){
            int oc = i & 31, ic = i >> 5;
            s_w[ic][oc] = g_clst[(icg*16 + ic)*512 + oc0 + oc];
        }
        __syncthreads();
        if (active){
#pragma unroll 4
            for (int ic = 0; ic < 16; ic++){
                float av = s_in[ic][p0], bv = s_in[ic][p1];
                ull ap = pack2(av, av), bp = pack2(bv, bv);
#pragma unroll
                for (int g = 0; g < 8; g++){
                    ulonglong2 w2 = *reinterpret_cast<const ulonglong2*>(&s_w[ic][g*4]);
                    fma2(acc0[2*g  ], ap, w2.x);
                    fma2(acc0[2*g+1], ap, w2.y);
                    fma2(acc1[2*g  ], bp, w2.x);
                    fma2(acc1[2*g+1], bp, w2.y);
                }
            }
        }
        __syncthreads();
    }
    if (active){
#pragma unroll
        for (int j = 0; j < 16; j++){
            int oc = oc0 + 2*j;
            float a0, a1, c0, c1;
            unpack2(acc0[j], a0, a1);
            unpack2(acc1[j], c0, c1);
            float bz0 = cls_b[oc], bz1 = cls_b[oc+1];
            s_c[2*j  ][p0] = fmaxf(a0+bz0, 0.f);
            s_c[2*j+1][p0] = fmaxf(a1+bz1, 0.f);
            s_c[2*j  ][p1] = fmaxf(c0+bz0, 0.f);
            s_c[2*j+1][p1] = fmaxf(c1+bz1, 0.f);
        }
    }
    __syncthreads();
    // 2x2 maxpool -> flat [ch*49 + py*7 + px]
    for (int i = t; i < 32*49; i += 128){
        int ocl = i/49, cell = i - ocl*49;
        int py = cell/7, px = cell - py*7;
        int base = 28*py + 2*px;
        float m = fmaxf(fmaxf(s_c[ocl][base], s_c[ocl][base+1]),
                        fmaxf(s_c[ocl][base+14], s_c[ocl][base+15]));
        g_FLAT[b*25088 + (oc0 + ocl)*49 + cell] = m;
    }
}

// ---------------- fc1: [64,25088] x [1024,25088]^T, k-split with atomics ----------------
__global__ void zero_fc1(){
    int i = blockIdx.x*blockDim.x + threadIdx.x;
    if (i < BB*1024) g_FC1[i] = 0.f;
}
__global__ void fc1_kernel(const float* __restrict__ w){
    int n0 = blockIdx.x*64;
    int k0 = blockIdx.y*1568;
    __shared__ float sA[64][33];
    __shared__ float sB[64][33];
    const int t = threadIdx.x;
    const int tx = t & 15, ty = t >> 4;
    float acc[4][4] = {};
    for (int kk = 0; kk < 1568; kk += 32){
        for (int i = t; i < 2048; i += 256){
            int row = i >> 5, k = i & 31;
            sA[row][k] = g_FLAT[row*25088 + k0 + kk + k];
            sB[row][k] = w[(n0+row)*25088 + k0 + kk + k];
        }
        __syncthreads();
#pragma unroll 8
        for (int k = 0; k < 32; k++){
            float a[4], bv[4];
#pragma unroll
            for (int i = 0; i < 4; i++) a[i] = sA[ty*4+i][k];
#pragma unroll
            for (int j = 0; j < 4; j++) bv[j] = sB[tx*4+j][k];
#pragma unroll
            for (int i = 0; i < 4; i++)
#pragma unroll
                for (int j = 0; j < 4; j++) acc[i][j] += a[i]*bv[j];
        }
        __syncthreads();
    }
#pragma unroll
    for (int i = 0; i < 4; i++)
#pragma unroll
        for (int j = 0; j < 4; j++)
            atomicAdd(&g_FC1[(ty*4+i)*1024 + n0 + tx*4 + j], acc[i][j]);
}

// ---------------- fc2: out = relu(fc1+b1) @ fc2_w^T + b2 ----------------
__global__ void fc2_kernel(const float* __restrict__ fc1_b, const float* __restrict__ w2,
                           const float* __restrict__ b2, float* __restrict__ out){
    int b = blockIdx.x;
    const int t = threadIdx.x;
    int n2 = t >> 3, kl = t & 7;
    float acc = 0.f;
    for (int k = kl; k < 1024; k += 8)
        acc += fmaxf(g_FC1[b*1024 + k] + fc1_b[k], 0.f) * w2[n2*1024 + k];
    __shared__ float red[256];
    red[t] = acc;
    __syncthreads();
    if (kl == 0){
        float s = red[t];
#pragma unroll
        for (int q = 1; q < 8; q++) s += red[t+q];
        out[b*32 + n2] = s + b2[n2];
    }
}

// ---------------- launch ----------------
extern "C" void kernel_launch(void* const* d_in, const int* in_sizes, int n_in,
                              void* d_out, int out_size){
    const float* feats    = (const float*)d_in[0];
    const int*   programs = (const int*)  d_in[1];
    const float* stem_w1  = (const float*)d_in[2];
    const float* stem_b1  = (const float*)d_in[3];
    const float* stem_w2  = (const float*)d_in[4];
    const float* stem_b2  = (const float*)d_in[5];
    const float* uw1      = (const float*)d_in[6];
    const float* ub1      = (const float*)d_in[7];
    const float* uw2      = (const float*)d_in[8];
    const float* ub2      = (const float*)d_in[9];
    const float* bwp      = (const float*)d_in[10];
    const float* bbp      = (const float*)d_in[11];
    const float* bw1      = (const float*)d_in[12];
    const float* bb1      = (const float*)d_in[13];
    const float* bw2      = (const float*)d_in[14];
    const float* bb2      = (const float*)d_in[15];
    const float* cls_w    = (const float*)d_in[16];
    const float* cls_b    = (const float*)d_in[17];
    const float* fc1_w    = (const float*)d_in[18];
    const float* fc1_b    = (const float*)d_in[19];
    const float* fc2_w    = (const float*)d_in[20];
    const float* fc2_b    = (const float*)d_in[21];
    float* out = (float*)d_out;

    // weight layout transforms (deterministic, every call)
    tr_stem1_k<<<1024, 256>>>(stem_w1);
    tr_stem2_k<<<256,  256>>>(stem_w2);
    tr_uw1_k  <<<1024, 256>>>(uw1);
    tr_uw2_k  <<<1024, 256>>>(uw2);
    tr_bw1_k  <<<1024, 256>>>(bw1);
    tr_bw2_k  <<<1024, 256>>>(bw2);
    tr_bwp_k  <<<256,  256>>>(bwp);
    tr_cls_k  <<<256,  256>>>(cls_w);

    // one persistent cluster kernel runs stem + the entire per-image program
    program_kernel<<<BB*4, 256>>>(feats, programs, stem_b1, stem_b2,
                                  ub1, ub2, bbp, bb1, bb2);

    cls_kernel<<<dim3(16, BB), 128>>>(cls_b);
    zero_fc1<<<256, 256>>>();
    fc1_kernel<<<dim3(16, 16), 256>>>(fc1_w);
    fc2_kernel<<<BB, 256>>>(fc1_b, fc2_w, fc2_b, out);
}